// round 15
// baseline (speedup 1.0000x reference)
#include <cuda_runtime.h>
#include <cuda_fp16.h>
#include <stdint.h>

// EdgeNetwork via register-fragment fp16 mma.sync, single-pass + work stealing.
//
//   B'[n][k], n in [0,544): n<512 -> B'[n][k] = Kmat[n*32+k]   (reshape(K,512,32))
//                           n>=512 -> bias[(n-512)*32+k]       (reshape(bias,32,32))
//   Per edge e: y[e,i] = sum_{blk=0..16} w[e,blk] * sum_j nb[e,j] * B'[blk*32+i][j]
//   w[e,blk] = bond[e,blk] (blk<16), 1.0 (blk=16, bias block).
//   out = segment_sum(y, src)
//
// Precision: C = f16(A) * f16(B), fp32 accumulate; rel_err 3.0e-4 measured (R13).
// R14: 16 -> 20 warps (640 thr). Profile shows latency-bound w/ no saturated pipe
// (tensor 34%, L1 53%, issue 29%); regs 84*640=53.8K fits, smem 180.7K fits.

#define NTH    640
#define NWARPS 20
#define GRID_X 148
#define NBLK   17

#define BF_BYTES  (NBLK * 4 * 2 * 32 * 8)   // 34816: Bfrag[blk][n8][v][lane] uint2
#define NB_STRIDE 36                        // f32 row stride (144B, 16B-aligned rows)
#define NB_BYTES  (32 * NB_STRIDE * 4)      // 4608 per warp (nb staging, reused for y)
#define BD_STRIDE 20                        // f32 row stride (80B, 16B-aligned rows)
#define BD_BYTES  (32 * BD_STRIDE * 4)      // 2560 per warp
#define DST_BYTES (32 * 4)

#define OFF_NB(wid)  (BF_BYTES + (wid) * NB_BYTES)
#define OFF_BD(wid)  (BF_BYTES + NWARPS * NB_BYTES + (wid) * BD_BYTES)
#define OFF_DS(wid)  (BF_BYTES + NWARPS * (NB_BYTES + BD_BYTES) + (wid) * DST_BYTES)
#define SMEM_BYTES   (BF_BYTES + NWARPS * (NB_BYTES + BD_BYTES + DST_BYTES))  // 180736

__device__ unsigned int g_tile_ctr;

// pack {f16(lo_val) in low 16, f16(hi_val) in high 16} with one instruction
__device__ __forceinline__ uint32_t pack_f16x2(float lo_val, float hi_val) {
    uint32_t r;
    asm("cvt.rn.f16x2.f32 %0, %1, %2;" : "=r"(r) : "f"(hi_val), "f"(lo_val));
    return r;
}

#define MMA16816(c0, c1, c2, c3, a0, a1, a2, a3, b0, b1)                        \
    asm volatile(                                                               \
        "mma.sync.aligned.m16n8k16.row.col.f32.f16.f16.f32 "                    \
        "{%0,%1,%2,%3}, {%4,%5,%6,%7}, {%8,%9}, {%0,%1,%2,%3};"                 \
        : "+f"(c0), "+f"(c1), "+f"(c2), "+f"(c3)                                \
        : "r"(a0), "r"(a1), "r"(a2), "r"(a3), "r"(b0), "r"(b1))

__global__ __launch_bounds__(NTH)
void edge_network_hmma(const float* __restrict__ atom,
                       const float* __restrict__ bond,
                       const int* __restrict__ pair,
                       const float* __restrict__ Kmat,
                       const float* __restrict__ bias,
                       float* __restrict__ out,
                       int n_edges, int n_wtiles)
{
    extern __shared__ __align__(16) char smem[];
    const int tid = threadIdx.x;
    const int w = tid >> 5, lane = tid & 31;

    // ---- one-time: build fp16 B fragment table in m16n8k16 B-operand order ----
    // idx = blk*256 + n8*64 + v*32 + lane;  v: 0 = k0-15, 1 = k16-31
    for (int idx = tid; idx < NBLK * 256; idx += NTH) {
        int li  = idx & 31;
        int v   = (idx >> 5) & 1;
        int n8  = (idx >> 6) & 3;
        int blk = idx >> 8;
        int n   = blk * 32 + n8 * 8 + (li >> 2);
        int kb  = v * 16 + (li & 3) * 2;
        const float* src = (n < 512) ? (Kmat + n * 32) : (bias + (n - 512) * 32);
        uint2 r;
        r.x = pack_f16x2(src[kb],     src[kb + 1]);
        r.y = pack_f16x2(src[kb + 8], src[kb + 9]);
        reinterpret_cast<uint2*>(smem)[idx] = r;
    }
    __syncthreads();

    float* nbsh  = (float*)(smem + OFF_NB(w));  // [32][36], reused as y-tile
    float* bdsh  = (float*)(smem + OFF_BD(w));  // [32][20], col 16 = 1.0 (bias weight)
    int*   dstw  = (int*)(smem + OFF_DS(w));
    const uint2* bft = reinterpret_cast<const uint2*>(smem);

    // ---- dynamic work stealing: lane 0 grabs tile indices ----
    int t;
    if (lane == 0) t = (int)atomicAdd(&g_tile_ctr, 1u);
    t = __shfl_sync(0xFFFFFFFFu, t, 0);

    while (t < n_wtiles) {
        int tn_l0;  // grab next tile now; ATOMG latency hides under this tile's work
        if (lane == 0) tn_l0 = (int)atomicAdd(&g_tile_ctr, 1u);

        const int e0 = t * 32;

        // ---- stage: 32 nb rows (gather) + bond rows; 2 lanes per edge, 2 passes ----
        #pragma unroll
        for (int p = 0; p < 2; p++) {
            int el = p * 16 + (lane >> 1);
            int e  = e0 + el;
            int hf = lane & 1;
            const float4 z = make_float4(0.f, 0.f, 0.f, 0.f);
            const float* asrc = nullptr;
            if (e < n_edges) asrc = atom + (size_t)pair[2 * e + 1] * 32 + hf * 16;
            #pragma unroll
            for (int q = 0; q < 4; q++) {
                float4 vv = asrc ? *reinterpret_cast<const float4*>(asrc + q * 4) : z;
                *reinterpret_cast<float4*>(&nbsh[el * NB_STRIDE + hf * 16 + q * 4]) = vv;
            }
            #pragma unroll
            for (int q = 0; q < 2; q++) {
                float4 vv = (e < n_edges)
                    ? *reinterpret_cast<const float4*>(bond + (size_t)e * 16 + hf * 8 + q * 4) : z;
                *reinterpret_cast<float4*>(&bdsh[el * BD_STRIDE + hf * 8 + q * 4]) = vv;
            }
        }
        {
            int e = e0 + lane;
            dstw[lane] = (e < n_edges) ? pair[2 * e] : -1;
            bdsh[lane * BD_STRIDE + 16] = 1.0f;  // bias-block weight
        }
        __syncwarp();

        // ---- build A fragments (fp16, single precision pass) ----
        uint32_t ahi[2][8];
        #pragma unroll
        for (int g = 0; g < 2; g++)
            #pragma unroll
            for (int kc = 0; kc < 2; kc++)
                #pragma unroll
                for (int q = 0; q < 4; q++) {
                    int r = g * 16 + (lane >> 2) + (q & 1) * 8;
                    int c = kc * 16 + (lane & 3) * 2 + (q >> 1) * 8;
                    float2 f = *reinterpret_cast<const float2*>(&nbsh[r * NB_STRIDE + c]);
                    ahi[g][kc * 4 + q] = pack_f16x2(f.x, f.y);
                }
        __syncwarp();  // all lanes done reading nbsh; safe to reuse it for y

        float yac[2][16];
        #pragma unroll
        for (int g = 0; g < 2; g++)
            #pragma unroll
            for (int i = 0; i < 16; i++) yac[g][i] = 0.f;

        // ---- main loop: 17 column-blocks; per block 16 MMAs (one depth-2 chain/group) ----
        #pragma unroll 1
        for (int blk = 0; blk < NBLK; blk++) {
            float w00 = bdsh[((lane >> 2) + 0)  * BD_STRIDE + blk];
            float w01 = bdsh[((lane >> 2) + 8)  * BD_STRIDE + blk];
            float w10 = bdsh[((lane >> 2) + 16) * BD_STRIDE + blk];
            float w11 = bdsh[((lane >> 2) + 24) * BD_STRIDE + blk];
            #pragma unroll
            for (int n8 = 0; n8 < 4; n8++) {
                const uint2* bp = bft + ((blk * 4 + n8) * 2) * 32 + lane;
                uint2 v0 = bp[0], v1 = bp[32];
                #pragma unroll
                for (int g = 0; g < 2; g++) {
                    float c0 = 0.f, c1 = 0.f, c2 = 0.f, c3 = 0.f;
                    MMA16816(c0, c1, c2, c3, ahi[g][0], ahi[g][1], ahi[g][2], ahi[g][3], v0.x, v0.y);
                    MMA16816(c0, c1, c2, c3, ahi[g][4], ahi[g][5], ahi[g][6], ahi[g][7], v1.x, v1.y);
                    float wa = g ? w10 : w00;
                    float wb = g ? w11 : w01;
                    yac[g][n8 * 4 + 0] = fmaf(wa, c0, yac[g][n8 * 4 + 0]);
                    yac[g][n8 * 4 + 1] = fmaf(wa, c1, yac[g][n8 * 4 + 1]);
                    yac[g][n8 * 4 + 2] = fmaf(wb, c2, yac[g][n8 * 4 + 2]);
                    yac[g][n8 * 4 + 3] = fmaf(wb, c3, yac[g][n8 * 4 + 3]);
                }
            }
        }

        // ---- y fragments -> smem (reuse nbsh) ----
        #pragma unroll
        for (int g = 0; g < 2; g++)
            #pragma unroll
            for (int n8 = 0; n8 < 4; n8++) {
                int r0 = g * 16 + (lane >> 2);
                int c  = n8 * 8 + (lane & 3) * 2;
                *reinterpret_cast<float2*>(&nbsh[r0 * NB_STRIDE + c]) =
                    make_float2(yac[g][n8 * 4 + 0], yac[g][n8 * 4 + 1]);
                *reinterpret_cast<float2*>(&nbsh[(r0 + 8) * NB_STRIDE + c]) =
                    make_float2(yac[g][n8 * 4 + 2], yac[g][n8 * 4 + 3]);
            }
        __syncwarp();

        // ---- scatter-add via vector red: 8 lanes x v4.f32 per edge, 4 edges/iter ----
        #pragma unroll 1
        for (int rr = 0; rr < 8; rr++) {
            int el = rr * 4 + (lane >> 3);
            int c  = (lane & 7) * 4;
            int d  = dstw[el];
            if (d >= 0) {
                float4 v = *reinterpret_cast<const float4*>(&nbsh[el * NB_STRIDE + c]);
                asm volatile("red.global.add.v4.f32 [%0], {%1,%2,%3,%4};"
                             :: "l"(out + (size_t)d * 32 + c),
                                "f"(v.x), "f"(v.y), "f"(v.z), "f"(v.w)
                             : "memory");
            }
        }
        __syncwarp();  // finish reading nbsh before next tile's staging overwrites it

        t = __shfl_sync(0xFFFFFFFFu, tn_l0, 0);
    }
}

extern "C" void kernel_launch(void* const* d_in, const int* in_sizes, int n_in,
                              void* d_out, int out_size) {
    const float* atom = (const float*)d_in[0];
    const float* bond = (const float*)d_in[1];
    const int*   pair = (const int*)d_in[2];
    const float* Kmat = (const float*)d_in[3];
    const float* bias = (const float*)d_in[4];
    float*       out  = (float*)d_out;

    const int n_edges  = in_sizes[1] / 16;
    const int n_wtiles = (n_edges + 31) / 32;

    cudaFuncSetAttribute(edge_network_hmma,
                         cudaFuncAttributeMaxDynamicSharedMemorySize, SMEM_BYTES);

    // reset the work-stealing counter + zero the poisoned output (both capturable)
    void* ctr_addr = nullptr;
    cudaGetSymbolAddress(&ctr_addr, g_tile_ctr);
    cudaMemsetAsync(ctr_addr, 0, sizeof(unsigned int), 0);
    cudaMemsetAsync(d_out, 0, (size_t)out_size * sizeof(float), 0);

    int nblocks = (n_wtiles + NWARPS - 1) / NWARPS;
    if (nblocks > GRID_X) nblocks = GRID_X;
    edge_network_hmma<<<nblocks, NTH, SMEM_BYTES>>>(atom, bond, pair, Kmat, bias, out,
                                                    n_edges, n_wtiles);
}